// round 16
// baseline (speedup 1.0000x reference)
#include <cuda_runtime.h>
#include <cstdint>

#define BB 1024
#define LL 400
#define TMM 150
#define EPSF 1e-5f
#define SEQW 5
#define NW 205   // ceil(BB / SEQW)

// ---------------- scratch (device globals; no allocations allowed) ----------
__device__ float g_xa[(size_t)BB * 3 * LL];        // [B,3,400]
__device__ float g_m0[(size_t)BB * TMM * 3];       // [B,150,3]
__device__ float g_s0[(size_t)BB * LL * 3];        // [B,400,3]
__device__ float g_a0[(size_t)BB * LL * 3];        // [B,400,3]

// ---------------- helpers ---------------------------------------------------
__device__ __forceinline__ float tanh_(float x) {
    float y;
    asm("tanh.approx.f32 %0, %1;" : "=f"(y) : "f"(x));
    return y;
}
__device__ __forceinline__ float sigm_(float x) {
    return fmaf(0.5f, tanh_(0.5f * x), 0.5f);
}

// ---------------- conv1d + BN(eval) + LeakyReLU -----------------------------
__global__ void k_conv(const float* __restrict__ x,
                       const float* __restrict__ cw, const float* __restrict__ cb,
                       const float* __restrict__ bw, const float* __restrict__ bb,
                       const float* __restrict__ bm, const float* __restrict__ bv) {
    int idx = blockIdx.x * blockDim.x + threadIdx.x;
    if (idx >= BB * LL) return;
    int b = idx / LL, t = idx % LL;
    const float* xb = x + (size_t)b * 3 * LL;
    float in[3][3];
#pragma unroll
    for (int ci = 0; ci < 3; ci++)
#pragma unroll
        for (int k = 0; k < 3; k++) {
            int tt = t + k - 1;
            in[ci][k] = (tt >= 0 && tt < LL) ? xb[ci * LL + tt] : 0.0f;
        }
#pragma unroll
    for (int co = 0; co < 3; co++) {
        float acc = cb[co];
#pragma unroll
        for (int ci = 0; ci < 3; ci++)
#pragma unroll
            for (int k = 0; k < 3; k++)
                acc = fmaf(cw[(co * 3 + ci) * 3 + k], in[ci][k], acc);
        float sc = bw[co] * rsqrtf(bv[co] + EPSF);
        acc = fmaf(acc - bm[co], sc, bb[co]);
        acc = (acc >= 0.0f) ? acc : 0.01f * acc;
        g_xa[((size_t)b * 3 + co) * LL + t] = acc;
    }
}

// ---------------- forward matmul: out[b,t,c] = sum_k xa[b,c,k]*M[b,k,t] -----
__global__ void k_mm_fwd(const float* __restrict__ M, float* __restrict__ out, int T) {
    int b = blockIdx.x;
    __shared__ float sxa[3][LL];
    for (int i = threadIdx.x; i < 3 * LL; i += blockDim.x)
        sxa[i / LL][i % LL] = g_xa[(size_t)b * 3 * LL + i];
    __syncthreads();
    int t = threadIdx.x;
    if (t >= T) return;
    const float* Mb = M + (size_t)b * LL * T + t;
    float a0 = 0.f, a1 = 0.f, a2 = 0.f;
#pragma unroll 8
    for (int k = 0; k < LL; k++) {
        float mv = Mb[(size_t)k * T];
        a0 = fmaf(sxa[0][k], mv, a0);
        a1 = fmaf(sxa[1][k], mv, a1);
        a2 = fmaf(sxa[2][k], mv, a2);
    }
    float* o = out + ((size_t)b * T + t) * 3;
    o[0] = a0; o[1] = a1; o[2] = a2;
}

// ---------------- fused 2-layer LSTM + LayerNorm, per-warp device body ------
// Software-pipelined (layer2 one step behind layer1), de-aliased SMEM buffers.
// pool: 2*SEQW*(3T+5) floats supplied by the caller.
__device__ __forceinline__ void lstm_ln_warp(
    float* __restrict__ pool, int lane,
    const float* __restrict__ Wih, const float* __restrict__ Whh,
    const float* __restrict__ bih, const float* __restrict__ bhh,
    const float* __restrict__ lnw, const float* __restrict__ lnb,
    const float* __restrict__ inp, float* __restrict__ outp,
    int T, int nB, int widx) {
    int T3 = 3 * T;
    int stride = T3 + 5;                 // odd -> coprime with 32 banks
    float* sxin = pool;
    float* shoutB = pool + SEQW * stride;
    int b0 = widx * SEQW;
    int nv = nB - b0; if (nv > SEQW) nv = SEQW;

    // ---- stage inputs into SMEM (coalesced) ----
    const float* src = inp + (size_t)b0 * T3;
    for (int s = 0; s < nv; s++)
        for (int i = lane; i < T3; i += 32)
            sxin[s * stride + i] = src[s * T3 + i];
    __syncwarp();

    // ---- lane mapping: 5 triples, lanes 15-31 shadow triple 4 ----
    int ln_ = (lane < 3 * SEQW) ? lane : (3 * SEQW - 1);
    int triple = ln_ / 3;
    int u = ln_ - triple * 3;
    int base = triple * 3;
    const float* xin = sxin + triple * stride;
    float* hout = shoutB + triple * stride;

    // ---- per-lane weights: gates (i,f,g,o) of unit u, layers 0/1 ----
    float wi1[4][3], wh1[4][3], b1[4], wi2[4][3], wh2[4][3], b2[4];
#pragma unroll
    for (int q = 0; q < 4; q++) {
        int gi = q * 3 + u;
#pragma unroll
        for (int v = 0; v < 3; v++) {
            wi1[q][v] = Wih[gi * 3 + v];
            wh1[q][v] = Whh[gi * 3 + v];
            wi2[q][v] = Wih[36 + gi * 3 + v];
            wh2[q][v] = Whh[36 + gi * 3 + v];
        }
        b1[q] = bih[gi] + bhh[gi];
        b2[q] = bih[12 + gi] + bhh[12 + gi];
    }

    float c1, c2 = 0.f;
    float h1a, h1b, h1c;
    float h2a = 0.f, h2b = 0.f, h2c = 0.f;
    float xc[4];

    // ---- prologue: layer1 step 0 ----
    {
        float x0 = xin[0], x1 = xin[1], x2 = xin[2];
#pragma unroll
        for (int q = 0; q < 4; q++)
            xc[q] = fmaf(x0, wi1[q][0], fmaf(x1, wi1[q][1], fmaf(x2, wi1[q][2], b1[q])));
        float si = sigm_(xc[0]), tg = tanh_(xc[2]), so = sigm_(xc[3]);
        c1 = si * tg;
        float h1u = so * tanh_(c1);
        h1a = __shfl_sync(0xffffffffu, h1u, base);
        h1b = __shfl_sync(0xffffffffu, h1u, base + 1);
        h1c = __shfl_sync(0xffffffffu, h1u, base + 2);
        int t13 = (T > 1) ? 3 : 0;
        float y0 = xin[t13], y1 = xin[t13 + 1], y2 = xin[t13 + 2];
#pragma unroll
        for (int q = 0; q < 4; q++)
            xc[q] = fmaf(y0, wi1[q][0], fmaf(y1, wi1[q][1], fmaf(y2, wi1[q][2], b1[q])));
    }

    // ---- body: layer2(t-1) and layer1(t), independent chains ----
    for (int t = 1; t < T; t++) {
        int tn3 = ((t + 1 < T) ? (t + 1) : t) * 3;
        float fx0 = xin[tn3], fx1 = xin[tn3 + 1], fx2 = xin[tn3 + 2];

        float g2[4];
#pragma unroll
        for (int q = 0; q < 4; q++)
            g2[q] = fmaf(h1a, wi2[q][0], fmaf(h1b, wi2[q][1], fmaf(h1c, wi2[q][2],
                    fmaf(h2a, wh2[q][0], fmaf(h2b, wh2[q][1], fmaf(h2c, wh2[q][2], b2[q]))))));

        float g1[4];
#pragma unroll
        for (int q = 0; q < 4; q++)
            g1[q] = fmaf(h1a, wh1[q][0], fmaf(h1b, wh1[q][1], fmaf(h1c, wh1[q][2], xc[q])));

        float si2 = sigm_(g2[0]), sf2 = sigm_(g2[1]), tg2 = tanh_(g2[2]), so2 = sigm_(g2[3]);
        float si1 = sigm_(g1[0]), sf1 = sigm_(g1[1]), tg1 = tanh_(g1[2]), so1 = sigm_(g1[3]);
        c2 = fmaf(sf2, c2, si2 * tg2);
        float h2u = so2 * tanh_(c2);
        c1 = fmaf(sf1, c1, si1 * tg1);
        float h1u = so1 * tanh_(c1);

        h1a = __shfl_sync(0xffffffffu, h1u, base);
        h1b = __shfl_sync(0xffffffffu, h1u, base + 1);
        h1c = __shfl_sync(0xffffffffu, h1u, base + 2);
        h2a = __shfl_sync(0xffffffffu, h2u, base);
        h2b = __shfl_sync(0xffffffffu, h2u, base + 1);
        h2c = __shfl_sync(0xffffffffu, h2u, base + 2);

#pragma unroll
        for (int q = 0; q < 4; q++)
            xc[q] = fmaf(fx0, wi1[q][0], fmaf(fx1, wi1[q][1], fmaf(fx2, wi1[q][2], b1[q])));

        hout[3 * (t - 1) + u] = h2u;
    }

    // ---- epilogue: layer2 step T-1 ----
    {
        float g2[4];
#pragma unroll
        for (int q = 0; q < 4; q++)
            g2[q] = fmaf(h1a, wi2[q][0], fmaf(h1b, wi2[q][1], fmaf(h1c, wi2[q][2],
                    fmaf(h2a, wh2[q][0], fmaf(h2b, wh2[q][1], fmaf(h2c, wh2[q][2], b2[q]))))));
        float si2 = sigm_(g2[0]), sf2 = sigm_(g2[1]), tg2 = tanh_(g2[2]), so2 = sigm_(g2[3]);
        c2 = fmaf(sf2, c2, si2 * tg2);
        float h2u = so2 * tanh_(c2);
        hout[3 * (T - 1) + u] = h2u;
    }
    __syncwarp();

    // ---- LayerNorm over (T,3), write transposed [3,T] ----
    float s1 = 0.f, s2 = 0.f;
    for (int t = 0; t < T; t++) {
        float v = hout[3 * t + u];
        s1 += v;
        s2 = fmaf(v, v, s2);
    }
    float sa = __shfl_sync(0xffffffffu, s1, base) +
               __shfl_sync(0xffffffffu, s1, base + 1) +
               __shfl_sync(0xffffffffu, s1, base + 2);
    float sq = __shfl_sync(0xffffffffu, s2, base) +
               __shfl_sync(0xffffffffu, s2, base + 1) +
               __shfl_sync(0xffffffffu, s2, base + 2);
    float invn = 1.0f / (float)T3;
    float mu = sa * invn;
    float var = sq * invn - mu * mu;
    float rs = rsqrtf(var + EPSF);

    int b = b0 + triple;
    bool ok = (lane < 3 * SEQW) && (b < nB);
    if (ok) {
        float* op = outp + (size_t)b * T3 + u * T;
        for (int t2 = 0; t2 < T / 2; t2++) {
            int t = 2 * t2;
            int i0 = 3 * t + u, i1 = 3 * t + 3 + u;
            float2 v;
            v.x = fmaf((hout[i0] - mu) * rs, lnw[i0], lnb[i0]);
            v.y = fmaf((hout[i1] - mu) * rs, lnw[i1], lnb[i1]);
            *reinterpret_cast<float2*>(op + t) = v;
        }
    }
}

// ---------------- M1: lstm_m (blocks [0,NW)) + fwd_side (blocks [NW,NW+BB)) -
// launch_bounds(256,2): regs<=128 (lstm uses ~99, no spill) -> 2 blocks/SM ->
// wave-1 holds 296 blocks >= all 205 lstm blocks: lstm hides under fwd BW.
__global__ void __launch_bounds__(256, 2)
k_m1(const float* __restrict__ S, float* __restrict__ outS,
     const float* __restrict__ mWih, const float* __restrict__ mWhh,
     const float* __restrict__ mbih, const float* __restrict__ mbhh,
     const float* __restrict__ mlnw, const float* __restrict__ mlnb,
     const float* __restrict__ gm0in, float* __restrict__ out_xm) {
    __shared__ float pool[2 * SEQW * (3 * TMM + 5)];   // 4550 floats
    if (blockIdx.x < NW) {
        if (threadIdx.x < 32)
            lstm_ln_warp(pool, threadIdx.x, mWih, mWhh, mbih, mbhh, mlnw, mlnb,
                         gm0in, out_xm, TMM, BB, blockIdx.x);
        return;
    }
    int b = blockIdx.x - NW;
    float* sxa = pool;                                  // 1200 floats
    for (int i = threadIdx.x; i < 3 * LL; i += 256)
        sxa[i] = g_xa[(size_t)b * 3 * LL + i];
    __syncthreads();
    for (int t = threadIdx.x; t < LL; t += 256) {
        const float* Mb = S + (size_t)b * LL * LL + t;
        float a0 = 0.f, a1 = 0.f, a2 = 0.f;
#pragma unroll 8
        for (int k = 0; k < LL; k++) {
            float mv = Mb[(size_t)k * LL];
            a0 = fmaf(sxa[k], mv, a0);
            a1 = fmaf(sxa[LL + k], mv, a1);
            a2 = fmaf(sxa[2 * LL + k], mv, a2);
        }
        float* o = outS + ((size_t)b * LL + t) * 3;
        o[0] = a0; o[1] = a1; o[2] = a2;
    }
}

// ---------------- M2: lstm_s (blocks [0,NW)) + bwd_main (blocks [NW,NW+BB)) -
__global__ void __launch_bounds__(256, 2)
k_m2(const float* __restrict__ sWih, const float* __restrict__ sWhh,
     const float* __restrict__ sbih, const float* __restrict__ sbhh,
     const float* __restrict__ slnw, const float* __restrict__ slnb,
     const float* __restrict__ gs0in, float* __restrict__ out_xs,
     const float* __restrict__ xm, const float* __restrict__ M) {
    __shared__ float pool[2 * SEQW * (3 * LL + 5)];    // 12050 floats
    if (blockIdx.x < NW) {
        if (threadIdx.x < 32)
            lstm_ln_warp(pool, threadIdx.x, sWih, sWhh, sbih, sbhh, slnw, slnb,
                         gs0in, out_xs, LL, BB, blockIdx.x);
        return;
    }
    int b = blockIdx.x - NW;
    float* sm_ = pool;                                  // 456 floats used
    const float* xmB = xm + (size_t)b * 3 * TMM;
    for (int i = threadIdx.x; i < 3 * TMM; i += 256)
        sm_[(i / TMM) * 152 + (i % TMM)] = xmB[i];
    __syncthreads();

    int warp = threadIdx.x >> 5, lane = threadIdx.x & 31;
    int grp = lane >> 3, gl = lane & 7;
    int rowsPerPass = 8 * 4;   // 8 warps * 4 groups

    for (int t0 = warp * 4 + grp; t0 < LL + 3; t0 += rowsPerPass) {
        bool valid = (t0 < LL);
        int t = valid ? t0 : (LL - 1);
        float a0 = 0.f, a1 = 0.f, a2 = 0.f;

        const float2* Mr = reinterpret_cast<const float2*>(M + ((size_t)b * LL + t) * TMM);
        for (int j2 = gl; j2 < TMM / 2; j2 += 8) {
            float2 v = Mr[j2];
            int j0 = 2 * j2;
            a0 = fmaf(sm_[j0], v.x, fmaf(sm_[j0 + 1], v.y, a0));
            a1 = fmaf(sm_[152 + j0], v.x, fmaf(sm_[152 + j0 + 1], v.y, a1));
            a2 = fmaf(sm_[304 + j0], v.x, fmaf(sm_[304 + j0 + 1], v.y, a2));
        }
#pragma unroll
        for (int o = 4; o; o >>= 1) {
            a0 += __shfl_xor_sync(0xffffffffu, a0, o);
            a1 += __shfl_xor_sync(0xffffffffu, a1, o);
            a2 += __shfl_xor_sync(0xffffffffu, a2, o);
        }
        if (gl == 0 && valid) {
            float* o = g_a0 + ((size_t)b * LL + t) * 3;
            o[0] = a0; o[1] = a1; o[2] = a2;
        }
    }
}

// ---------------- bwd SIDE half: g_a0[b,t,c] += sum_k xs[b,c,k]*side[b,t,k] -
__global__ void k_mm_bwd_s(const float* __restrict__ xs,   // [B,3,400]
                           const float* __restrict__ S) {  // [B,400,400]
    int b = blockIdx.x;
    __shared__ float ss_[3 * LL];
    const float* xsB = xs + (size_t)b * 3 * LL;
    for (int i = threadIdx.x; i < 3 * LL; i += blockDim.x)
        ss_[i] = xsB[i];
    __syncthreads();

    int warp = threadIdx.x >> 5, lane = threadIdx.x & 31;
    int grp = lane >> 3, gl = lane & 7;
    int rowsPerPass = (blockDim.x >> 5) * 4;

    for (int t0 = warp * 4 + grp; t0 < LL + 3; t0 += rowsPerPass) {
        bool valid = (t0 < LL);
        int t = valid ? t0 : (LL - 1);
        float a0 = 0.f, a1 = 0.f, a2 = 0.f;

        const float4* Sr = reinterpret_cast<const float4*>(S + ((size_t)b * LL + t) * LL);
        for (int k4 = gl; k4 < LL / 4; k4 += 8) {
            float4 v = Sr[k4];
            int k0 = 4 * k4;
            a0 = fmaf(ss_[k0], v.x, fmaf(ss_[k0 + 1], v.y, fmaf(ss_[k0 + 2], v.z, fmaf(ss_[k0 + 3], v.w, a0))));
            a1 = fmaf(ss_[LL + k0], v.x, fmaf(ss_[LL + k0 + 1], v.y, fmaf(ss_[LL + k0 + 2], v.z, fmaf(ss_[LL + k0 + 3], v.w, a1))));
            a2 = fmaf(ss_[2 * LL + k0], v.x, fmaf(ss_[2 * LL + k0 + 1], v.y, fmaf(ss_[2 * LL + k0 + 2], v.z, fmaf(ss_[2 * LL + k0 + 3], v.w, a2))));
        }
#pragma unroll
        for (int o = 4; o; o >>= 1) {
            a0 += __shfl_xor_sync(0xffffffffu, a0, o);
            a1 += __shfl_xor_sync(0xffffffffu, a1, o);
            a2 += __shfl_xor_sync(0xffffffffu, a2, o);
        }
        if (gl == 0 && valid) {
            float* o = g_a0 + ((size_t)b * LL + t) * 3;
            o[0] += a0; o[1] += a1; o[2] += a2;
        }
    }
}

// ---------------- standalone LSTM (a-branch) --------------------------------
__global__ void __launch_bounds__(32)
k_lstm_a(const float* __restrict__ Wih, const float* __restrict__ Whh,
         const float* __restrict__ bih, const float* __restrict__ bhh,
         const float* __restrict__ lnw, const float* __restrict__ lnb,
         const float* __restrict__ inp, float* __restrict__ outp) {
    __shared__ float pool[2 * SEQW * (3 * LL + 5)];    // 12050 floats
    lstm_ln_warp(pool, threadIdx.x & 31, Wih, Whh, bih, bhh, lnw, lnb,
                 inp, outp, LL, BB, blockIdx.x);
}

// ---------------- launch ----------------------------------------------------
extern "C" void kernel_launch(void* const* d_in, const int* in_sizes, int n_in,
                              void* d_out, int out_size) {
    (void)in_sizes; (void)n_in; (void)out_size;
    const float* x      = (const float*)d_in[0];
    const float* mainp  = (const float*)d_in[1];
    const float* sidep  = (const float*)d_in[2];
    const float* conv_w = (const float*)d_in[3];
    const float* conv_b = (const float*)d_in[4];
    const float* bn_w   = (const float*)d_in[5];
    const float* bn_b   = (const float*)d_in[6];
    const float* bn_m   = (const float*)d_in[7];
    const float* bn_v   = (const float*)d_in[8];
    const float* m_Wih = (const float*)d_in[9];
    const float* m_Whh = (const float*)d_in[10];
    const float* m_bih = (const float*)d_in[11];
    const float* m_bhh = (const float*)d_in[12];
    const float* m_lnw = (const float*)d_in[13];
    const float* m_lnb = (const float*)d_in[14];
    const float* s_Wih = (const float*)d_in[15];
    const float* s_Whh = (const float*)d_in[16];
    const float* s_bih = (const float*)d_in[17];
    const float* s_bhh = (const float*)d_in[18];
    const float* s_lnw = (const float*)d_in[19];
    const float* s_lnb = (const float*)d_in[20];
    const float* a_Wih = (const float*)d_in[21];
    const float* a_Whh = (const float*)d_in[22];
    const float* a_bih = (const float*)d_in[23];
    const float* a_bhh = (const float*)d_in[24];
    const float* a_lnw = (const float*)d_in[25];
    const float* a_lnb = (const float*)d_in[26];

    float* out = (float*)d_out;
    float* out_xm  = out;                                   // [B,3,150]
    float* out_xs  = out + (size_t)BB * 3 * TMM;            // [B,3,400]
    float* out_xa  = out + (size_t)BB * 3 * (TMM + LL);     // [B,3,400]

    float* gm0; cudaGetSymbolAddress((void**)&gm0, g_m0);
    float* gs0; cudaGetSymbolAddress((void**)&gs0, g_s0);
    float* ga0; cudaGetSymbolAddress((void**)&ga0, g_a0);

    // 1. conv + bn + leakyrelu -> g_xa
    k_conv<<<(BB * LL + 255) / 256, 256>>>(x, conv_w, conv_b, bn_w, bn_b, bn_m, bn_v);
    // 2. xm_pre = xa @ main -> g_m0 [B,150,3]
    k_mm_fwd<<<BB, 160>>>(mainp, gm0, TMM);
    // 3. M1: lstm_m (hidden) + fwd_side -> out_xm, g_s0
    k_m1<<<NW + BB, 256>>>(sidep, gs0,
                           m_Wih, m_Whh, m_bih, m_bhh, m_lnw, m_lnb,
                           gm0, out_xm);
    // 4. M2: lstm_s + bwd_main (hidden) -> out_xs, g_a0(main part)
    k_m2<<<NW + BB, 256>>>(s_Wih, s_Whh, s_bih, s_bhh, s_lnw, s_lnb,
                           gs0, out_xs, out_xm, mainp);
    // 5. bwd_side accumulate -> g_a0
    k_mm_bwd_s<<<BB, 512>>>(out_xs, sidep);
    // 6. lstm_a -> out_xa
    k_lstm_a<<<NW, 32>>>(a_Wih, a_Whh, a_bih, a_bhh, a_lnw, a_lnb,
                         ga0, out_xa);
}

// round 17
// speedup vs baseline: 1.3262x; 1.3262x over previous
#include <cuda_runtime.h>
#include <cstdint>

#define BB 1024
#define LL 400
#define TMM 150
#define EPSF 1e-5f
#define SEQW 5

// ---------------- scratch (device globals; no allocations allowed) ----------
__device__ float g_m0[(size_t)BB * TMM * 3];       // [B,150,3]
__device__ float g_s0[(size_t)BB * LL * 3];        // [B,400,3]
__device__ float g_a0[(size_t)BB * LL * 3];        // [B,400,3]

// ---------------- helpers ---------------------------------------------------
__device__ __forceinline__ float tanh_(float x) {
    float y;
    asm("tanh.approx.f32 %0, %1;" : "=f"(y) : "f"(x));
    return y;
}
__device__ __forceinline__ float sigm_(float x) {
    return fmaf(0.5f, tanh_(0.5f * x), 0.5f);
}

// ---- in-block conv+BN+LeakyReLU: x[b] (smem) -> xa[b] (smem), same math as
// the old k_conv (identical FMA order -> bitwise identical results).
__device__ __forceinline__ void conv_block(const float* __restrict__ xg,  // x + b*3*LL
                                           float (*sx)[LL], float (*sxa)[LL],
                                           const float* __restrict__ cw,
                                           const float* __restrict__ cb,
                                           const float* __restrict__ bw,
                                           const float* __restrict__ bb,
                                           const float* __restrict__ bm,
                                           const float* __restrict__ bv,
                                           int tid, int nthr) {
    for (int i = tid; i < 3 * LL; i += nthr)
        sx[i / LL][i % LL] = xg[i];
    __syncthreads();
    for (int t = tid; t < LL; t += nthr) {
        float in[3][3];
#pragma unroll
        for (int ci = 0; ci < 3; ci++)
#pragma unroll
            for (int k = 0; k < 3; k++) {
                int tt = t + k - 1;
                in[ci][k] = (tt >= 0 && tt < LL) ? sx[ci][tt] : 0.0f;
            }
#pragma unroll
        for (int co = 0; co < 3; co++) {
            float acc = cb[co];
#pragma unroll
            for (int ci = 0; ci < 3; ci++)
#pragma unroll
                for (int k = 0; k < 3; k++)
                    acc = fmaf(cw[(co * 3 + ci) * 3 + k], in[ci][k], acc);
            float sc = bw[co] * rsqrtf(bv[co] + EPSF);
            acc = fmaf(acc - bm[co], sc, bb[co]);
            acc = (acc >= 0.0f) ? acc : 0.01f * acc;
            sxa[co][t] = acc;
        }
    }
    __syncthreads();
}

// ---------------- fused conv + forward matmul -------------------------------
// out[b,t,c] = sum_k xa[b,c,k]*M[b,k,t]; xa computed in-block from x.
__global__ void k_conv_mm_fwd(const float* __restrict__ x,
                              const float* __restrict__ cw, const float* __restrict__ cb,
                              const float* __restrict__ bw, const float* __restrict__ bb,
                              const float* __restrict__ bm, const float* __restrict__ bv,
                              const float* __restrict__ M, float* __restrict__ out, int T) {
    int b = blockIdx.x;
    __shared__ float sx[3][LL];
    __shared__ float sxa[3][LL];
    conv_block(x + (size_t)b * 3 * LL, sx, sxa, cw, cb, bw, bb, bm, bv,
               threadIdx.x, blockDim.x);
    int t = threadIdx.x;
    if (t >= T) return;
    const float* Mb = M + (size_t)b * LL * T + t;
    float a0 = 0.f, a1 = 0.f, a2 = 0.f;
#pragma unroll 8
    for (int k = 0; k < LL; k++) {
        float mv = Mb[(size_t)k * T];
        a0 = fmaf(sxa[0][k], mv, a0);
        a1 = fmaf(sxa[1][k], mv, a1);
        a2 = fmaf(sxa[2][k], mv, a2);
    }
    float* o = out + ((size_t)b * T + t) * 3;
    o[0] = a0; o[1] = a1; o[2] = a2;
}

// ---------------- fused transpose matmul, 8-LANE-GROUP per row --------------
__global__ void k_mm_bwd(const float* __restrict__ xm,   // [B,3,150]
                         const float* __restrict__ xs,   // [B,3,400]
                         const float* __restrict__ M,    // [B,400,150]
                         const float* __restrict__ S) {  // [B,400,400]
    int b = blockIdx.x;
    __shared__ float sm_[3 * 152];
    __shared__ float ss_[3 * LL];
    const float* xmB = xm + (size_t)b * 3 * TMM;
    const float* xsB = xs + (size_t)b * 3 * LL;
    for (int i = threadIdx.x; i < 3 * TMM; i += blockDim.x)
        sm_[(i / TMM) * 152 + (i % TMM)] = xmB[i];
    for (int i = threadIdx.x; i < 3 * LL; i += blockDim.x)
        ss_[i] = xsB[i];
    __syncthreads();

    int warp = threadIdx.x >> 5, lane = threadIdx.x & 31;
    int grp = lane >> 3, gl = lane & 7;
    int rowsPerPass = (blockDim.x >> 5) * 4;

    for (int t0 = warp * 4 + grp; t0 < LL + 3; t0 += rowsPerPass) {
        bool valid = (t0 < LL);
        int t = valid ? t0 : (LL - 1);

        float a0 = 0.f, a1 = 0.f, a2 = 0.f;

        const float4* Sr = reinterpret_cast<const float4*>(S + ((size_t)b * LL + t) * LL);
        for (int k4 = gl; k4 < LL / 4; k4 += 8) {
            float4 v = Sr[k4];
            int k0 = 4 * k4;
            a0 = fmaf(ss_[k0], v.x, fmaf(ss_[k0 + 1], v.y, fmaf(ss_[k0 + 2], v.z, fmaf(ss_[k0 + 3], v.w, a0))));
            a1 = fmaf(ss_[LL + k0], v.x, fmaf(ss_[LL + k0 + 1], v.y, fmaf(ss_[LL + k0 + 2], v.z, fmaf(ss_[LL + k0 + 3], v.w, a1))));
            a2 = fmaf(ss_[2 * LL + k0], v.x, fmaf(ss_[2 * LL + k0 + 1], v.y, fmaf(ss_[2 * LL + k0 + 2], v.z, fmaf(ss_[2 * LL + k0 + 3], v.w, a2))));
        }

        const float2* Mr = reinterpret_cast<const float2*>(M + ((size_t)b * LL + t) * TMM);
        for (int j2 = gl; j2 < TMM / 2; j2 += 8) {
            float2 v = Mr[j2];
            int j0 = 2 * j2;
            a0 = fmaf(sm_[j0], v.x, fmaf(sm_[j0 + 1], v.y, a0));
            a1 = fmaf(sm_[152 + j0], v.x, fmaf(sm_[152 + j0 + 1], v.y, a1));
            a2 = fmaf(sm_[304 + j0], v.x, fmaf(sm_[304 + j0 + 1], v.y, a2));
        }

#pragma unroll
        for (int o = 4; o; o >>= 1) {
            a0 += __shfl_xor_sync(0xffffffffu, a0, o);
            a1 += __shfl_xor_sync(0xffffffffu, a1, o);
            a2 += __shfl_xor_sync(0xffffffffu, a2, o);
        }
        if (gl == 0 && valid) {
            float* o = g_a0 + ((size_t)b * LL + t) * 3;
            o[0] = a0; o[1] = a1; o[2] = a2;
        }
    }
}

// ---------------- fused 2-layer LSTM + LayerNorm, SMEM-resident -------------
// SOFTWARE-PIPELINED: layer 2 runs one step behind layer 1 (R14-exact).
__global__ void __launch_bounds__(32)
k_lstm_ln(const float* __restrict__ Wih0, const float* __restrict__ Whh0,
          const float* __restrict__ bih0, const float* __restrict__ bhh0,
          const float* __restrict__ lnw0, const float* __restrict__ lnb0,
          const float* __restrict__ in0, float* __restrict__ out0,
          int T0, int nB0, int nW0,
          const float* __restrict__ Wih1, const float* __restrict__ Whh1,
          const float* __restrict__ bih1, const float* __restrict__ bhh1,
          const float* __restrict__ lnw1, const float* __restrict__ lnb1,
          const float* __restrict__ in1, float* __restrict__ out1,
          int T1, int nB1) {
    __shared__ float sxin[SEQW * (3 * LL + 5)];   // 6025 words
    __shared__ float shout[SEQW * (3 * LL + 5)];  // 6025 words
    int warpId = blockIdx.x;
    int lane = threadIdx.x & 31;

    bool first = (warpId < nW0);
    const float* Wih = first ? Wih0 : Wih1;
    const float* Whh = first ? Whh0 : Whh1;
    const float* bih = first ? bih0 : bih1;
    const float* bhh = first ? bhh0 : bhh1;
    const float* lnw = first ? lnw0 : lnw1;
    const float* lnb = first ? lnb0 : lnb1;
    const float* inp = first ? in0 : in1;
    float* outp = first ? out0 : out1;
    int T  = first ? T0 : T1;
    int nB = first ? nB0 : nB1;
    int widx = first ? warpId : (warpId - nW0);

    int T3 = 3 * T;
    int stride = T3 + 5;                 // odd -> coprime with 32 banks
    int b0 = widx * SEQW;
    int nv = nB - b0; if (nv > SEQW) nv = SEQW;

    // ---- stage inputs into SMEM (coalesced) ----
    const float* src = inp + (size_t)b0 * T3;
    for (int s = 0; s < nv; s++)
        for (int i = lane; i < T3; i += 32)
            sxin[s * stride + i] = src[s * T3 + i];
    __syncwarp();

    // ---- lane mapping: 5 triples, lanes 15-31 shadow triple 4 ----
    int ln_ = (lane < 3 * SEQW) ? lane : (3 * SEQW - 1);
    int triple = ln_ / 3;
    int u = ln_ - triple * 3;
    int base = triple * 3;
    const float* xin = sxin + triple * stride;
    float* hout = shout + triple * stride;

    // ---- per-lane weights: gates (i,f,g,o) of unit u, layers 0/1 ----
    float wi1[4][3], wh1[4][3], b1[4], wi2[4][3], wh2[4][3], b2[4];
#pragma unroll
    for (int q = 0; q < 4; q++) {
        int gi = q * 3 + u;
#pragma unroll
        for (int v = 0; v < 3; v++) {
            wi1[q][v] = Wih[gi * 3 + v];
            wh1[q][v] = Whh[gi * 3 + v];
            wi2[q][v] = Wih[36 + gi * 3 + v];
            wh2[q][v] = Whh[36 + gi * 3 + v];
        }
        b1[q] = bih[gi] + bhh[gi];
        b2[q] = bih[12 + gi] + bhh[12 + gi];
    }

    float c1, c2 = 0.f;
    float h1a, h1b, h1c;
    float h2a = 0.f, h2b = 0.f, h2c = 0.f;
    float xc[4];

    // ---- prologue: layer1 step 0 (h1(-1)=0, c1(-1)=0) ----
    {
        float x0 = xin[0], x1 = xin[1], x2 = xin[2];
#pragma unroll
        for (int q = 0; q < 4; q++)
            xc[q] = fmaf(x0, wi1[q][0], fmaf(x1, wi1[q][1], fmaf(x2, wi1[q][2], b1[q])));
        float si = sigm_(xc[0]), tg = tanh_(xc[2]), so = sigm_(xc[3]);
        c1 = si * tg;
        float h1u = so * tanh_(c1);
        h1a = __shfl_sync(0xffffffffu, h1u, base);
        h1b = __shfl_sync(0xffffffffu, h1u, base + 1);
        h1c = __shfl_sync(0xffffffffu, h1u, base + 2);
        int t13 = (T > 1) ? 3 : 0;
        float y0 = xin[t13], y1 = xin[t13 + 1], y2 = xin[t13 + 2];
#pragma unroll
        for (int q = 0; q < 4; q++)
            xc[q] = fmaf(y0, wi1[q][0], fmaf(y1, wi1[q][1], fmaf(y2, wi1[q][2], b1[q])));
    }

    // ---- body t = 1..T-1: layer2(t-1) and layer1(t), independent chains ----
    for (int t = 1; t < T; t++) {
        int tn3 = ((t + 1 < T) ? (t + 1) : t) * 3;
        float fx0 = xin[tn3], fx1 = xin[tn3 + 1], fx2 = xin[tn3 + 2];

        // chain B: layer2 step t-1 (uses h1(t-1), h2(t-2))
        float g2[4];
#pragma unroll
        for (int q = 0; q < 4; q++)
            g2[q] = fmaf(h1a, wi2[q][0], fmaf(h1b, wi2[q][1], fmaf(h1c, wi2[q][2],
                    fmaf(h2a, wh2[q][0], fmaf(h2b, wh2[q][1], fmaf(h2c, wh2[q][2], b2[q]))))));

        // chain A: layer1 step t (uses h1(t-1), xc(t))
        float g1[4];
#pragma unroll
        for (int q = 0; q < 4; q++)
            g1[q] = fmaf(h1a, wh1[q][0], fmaf(h1b, wh1[q][1], fmaf(h1c, wh1[q][2], xc[q])));

        float si2 = sigm_(g2[0]), sf2 = sigm_(g2[1]), tg2 = tanh_(g2[2]), so2 = sigm_(g2[3]);
        float si1 = sigm_(g1[0]), sf1 = sigm_(g1[1]), tg1 = tanh_(g1[2]), so1 = sigm_(g1[3]);
        c2 = fmaf(sf2, c2, si2 * tg2);
        float h2u = so2 * tanh_(c2);
        c1 = fmaf(sf1, c1, si1 * tg1);
        float h1u = so1 * tanh_(c1);

        h1a = __shfl_sync(0xffffffffu, h1u, base);
        h1b = __shfl_sync(0xffffffffu, h1u, base + 1);
        h1c = __shfl_sync(0xffffffffu, h1u, base + 2);
        h2a = __shfl_sync(0xffffffffu, h2u, base);
        h2b = __shfl_sync(0xffffffffu, h2u, base + 1);
        h2c = __shfl_sync(0xffffffffu, h2u, base + 2);

        // xc(t+1), off both chains
#pragma unroll
        for (int q = 0; q < 4; q++)
            xc[q] = fmaf(fx0, wi1[q][0], fmaf(fx1, wi1[q][1], fmaf(fx2, wi1[q][2], b1[q])));

        hout[3 * (t - 1) + u] = h2u;
    }

    // ---- epilogue: layer2 step T-1 ----
    {
        float g2[4];
#pragma unroll
        for (int q = 0; q < 4; q++)
            g2[q] = fmaf(h1a, wi2[q][0], fmaf(h1b, wi2[q][1], fmaf(h1c, wi2[q][2],
                    fmaf(h2a, wh2[q][0], fmaf(h2b, wh2[q][1], fmaf(h2c, wh2[q][2], b2[q]))))));
        float si2 = sigm_(g2[0]), sf2 = sigm_(g2[1]), tg2 = tanh_(g2[2]), so2 = sigm_(g2[3]);
        c2 = fmaf(sf2, c2, si2 * tg2);
        float h2u = so2 * tanh_(c2);
        hout[3 * (T - 1) + u] = h2u;
    }
    __syncwarp();

    // ---- LayerNorm over (T,3) per sequence, write transposed [3,T] ----
    float s1 = 0.f, s2 = 0.f;
    for (int t = 0; t < T; t++) {
        float v = hout[3 * t + u];
        s1 += v;
        s2 = fmaf(v, v, s2);
    }
    float sa = __shfl_sync(0xffffffffu, s1, base) +
               __shfl_sync(0xffffffffu, s1, base + 1) +
               __shfl_sync(0xffffffffu, s1, base + 2);
    float sq = __shfl_sync(0xffffffffu, s2, base) +
               __shfl_sync(0xffffffffu, s2, base + 1) +
               __shfl_sync(0xffffffffu, s2, base + 2);
    float invn = 1.0f / (float)T3;
    float mu = sa * invn;
    float var = sq * invn - mu * mu;
    float rs = rsqrtf(var + EPSF);

    int b = b0 + triple;
    bool ok = (lane < 3 * SEQW) && (b < nB);
    if (ok) {
        float* op = outp + (size_t)b * T3 + u * T;   // [B,3,T], row u
        for (int t2 = 0; t2 < T / 2; t2++) {
            int t = 2 * t2;
            int i0 = 3 * t + u, i1 = 3 * t + 3 + u;
            float2 v;
            v.x = fmaf((hout[i0] - mu) * rs, lnw[i0], lnb[i0]);
            v.y = fmaf((hout[i1] - mu) * rs, lnw[i1], lnb[i1]);
            *reinterpret_cast<float2*>(op + t) = v;
        }
    }
}

// ---------------- launch ----------------------------------------------------
extern "C" void kernel_launch(void* const* d_in, const int* in_sizes, int n_in,
                              void* d_out, int out_size) {
    (void)in_sizes; (void)n_in; (void)out_size;
    const float* x      = (const float*)d_in[0];
    const float* mainp  = (const float*)d_in[1];
    const float* sidep  = (const float*)d_in[2];
    const float* conv_w = (const float*)d_in[3];
    const float* conv_b = (const float*)d_in[4];
    const float* bn_w   = (const float*)d_in[5];
    const float* bn_b   = (const float*)d_in[6];
    const float* bn_m   = (const float*)d_in[7];
    const float* bn_v   = (const float*)d_in[8];
    const float* m_Wih = (const float*)d_in[9];
    const float* m_Whh = (const float*)d_in[10];
    const float* m_bih = (const float*)d_in[11];
    const float* m_bhh = (const float*)d_in[12];
    const float* m_lnw = (const float*)d_in[13];
    const float* m_lnb = (const float*)d_in[14];
    const float* s_Wih = (const float*)d_in[15];
    const float* s_Whh = (const float*)d_in[16];
    const float* s_bih = (const float*)d_in[17];
    const float* s_bhh = (const float*)d_in[18];
    const float* s_lnw = (const float*)d_in[19];
    const float* s_lnb = (const float*)d_in[20];
    const float* a_Wih = (const float*)d_in[21];
    const float* a_Whh = (const float*)d_in[22];
    const float* a_bih = (const float*)d_in[23];
    const float* a_bhh = (const float*)d_in[24];
    const float* a_lnw = (const float*)d_in[25];
    const float* a_lnb = (const float*)d_in[26];

    float* out = (float*)d_out;
    float* out_xm  = out;                                   // [B,3,150]
    float* out_xs  = out + (size_t)BB * 3 * TMM;            // [B,3,400]
    float* out_xa  = out + (size_t)BB * 3 * (TMM + LL);     // [B,3,400]

    float* gm0; cudaGetSymbolAddress((void**)&gm0, g_m0);
    float* gs0; cudaGetSymbolAddress((void**)&gs0, g_s0);
    float* ga0; cudaGetSymbolAddress((void**)&ga0, g_a0);

    int nW = (BB + SEQW - 1) / SEQW;   // 205

    // 1. conv fused into fwd_m: xm_pre = conv(x) @ main -> g_m0 [B,150,3]
    k_conv_mm_fwd<<<BB, 160>>>(x, conv_w, conv_b, bn_w, bn_b, bn_m, bn_v,
                               mainp, gm0, TMM);
    // 2. conv fused into fwd_s: xs_pre = conv(x) @ side -> g_s0 [B,400,3]
    k_conv_mm_fwd<<<BB, 416>>>(x, conv_w, conv_b, bn_w, bn_b, bn_m, bn_v,
                               sidep, gs0, LL);
    // 3. LSTM+LN m & s -> out_xm, out_xs (transposed)
    k_lstm_ln<<<2 * nW, 32>>>(m_Wih, m_Whh, m_bih, m_bhh, m_lnw, m_lnb,
                              gm0, out_xm, TMM, BB, nW,
                              s_Wih, s_Whh, s_bih, s_bhh, s_lnw, s_lnb,
                              gs0, out_xs, LL, BB);
    // 4. xall_pre = xm @ main^T + xs @ side^T -> g_a0 (8-lane-group rows)
    k_mm_bwd<<<BB, 512>>>(out_xm, out_xs, mainp, sidep);
    // 5. LSTM+LN a -> out_xa
    k_lstm_ln<<<nW, 32>>>(a_Wih, a_Whh, a_bih, a_bhh, a_lnw, a_lnb,
                          ga0, out_xa, LL, BB, nW,
                          a_Wih, a_Whh, a_bih, a_bhh, a_lnw, a_lnb,
                          ga0, out_xa, LL, 0);
}